// round 3
// baseline (speedup 1.0000x reference)
#include <cuda_runtime.h>
#include <math.h>

// ---------------- problem constants ----------------
#define N_SRC   50000
#define N_DST   50000
#define E_NUM   800000
#define IN_NODE 128
#define OUT_NODE 64
#define NHEAD   4
#define HN      (NHEAD*OUT_NODE)   // 256
#define HE      64                 // NHEAD*OUT_EDGE
#define NCAT    (HN + HE)          // 320 = [W_ns | W_ni] output cols
#define SLOPE   0.01f
#define OUT_ELEMS (N_DST*OUT_NODE) // 3,200,000

// ---------------- scratch (device globals; allocation-free) ----------------
// g_proj row layout: cols [0,256) = h_src (4 heads x 64), cols [256,320) = f_ni
__device__ __align__(16) float g_proj[(size_t)N_SRC * NCAT];   // 64 MB
__device__ __align__(16) float g_fnj [(size_t)N_DST * HE];     // 12.8 MB
__device__ __align__(16) float g_a   [(size_t)E_NUM * NHEAD];
__device__ __align__(16) float g_s   [(size_t)N_DST * NHEAD];
__device__ __align__(16) float g_wcat[IN_NODE * NCAT];         // [W_ns | W_ni]
__device__ __align__(16) float g_bcat[NCAT];                   // [b_ns | 0]
__device__ __align__(16) float g_wsum[HE];                     // colsum(W_fij)

// ---------------- helpers ----------------
__device__ __forceinline__ void redAddF4(float4* p, float4 v) {
    asm volatile("red.global.add.v4.f32 [%0], {%1, %2, %3, %4};"
                 :: "l"(__cvta_generic_to_global(p)),
                    "f"(v.x), "f"(v.y), "f"(v.z), "f"(v.w)
                 : "memory");
}
__device__ __forceinline__ void redAddF1(float* p, float v) {
    asm volatile("red.global.add.f32 [%0], %1;"
                 :: "l"(__cvta_generic_to_global(p)), "f"(v) : "memory");
}
__device__ __forceinline__ float leaky(float x) {
    return x >= 0.f ? x : SLOPE * x;
}

// ---------------- init: zero out, s=0 ----------------
__global__ void init_kernel(float* __restrict__ out) {
    int i = blockIdx.x * blockDim.x + threadIdx.x;   // exact 3,200,000
    out[i] = 0.f;
    if (i < N_DST * NHEAD) g_s[i] = 0.f;
}

// ---------------- prep: wsum, bias concat ----------------
__global__ void prep_misc(const float* __restrict__ W_fij,
                          const float* __restrict__ b_ns) {
    int t = threadIdx.x;   // 320 threads
    if (t < HE) {
        float s = 0.f;
#pragma unroll
        for (int k = 0; k < 16; k++) s += W_fij[k * HE + t];
        g_wsum[t] = s;
    }
    g_bcat[t] = (t < HN) ? b_ns[t] : 0.f;
}

// ---------------- prep: weight concat [W_ns | W_ni] -> 128 x 320 -----------
__global__ void prep_wcat(const float* __restrict__ W_ns,
                          const float* __restrict__ W_ni) {
    int i = blockIdx.x * blockDim.x + threadIdx.x;   // exact 128*320 = 40960
    int k = i / NCAT, n = i % NCAT;
    g_wcat[i] = (n < HN) ? W_ns[k * HN + n] : W_ni[k * HE + (n - HN)];
}

// ---------------- unified SGEMM (all three projections, one launch) --------
// grid = (391, 6).  y<5: g_proj = nfeats @ [W_ns|W_ni] + [b_ns|0]  (N=320)
//                   y==5: g_fnj = dst_feats @ W_nj                  (N=64)
// BM=128, BN=64, BK=16, 256 threads, TM=4, TN=8, double-buffered smem.
#define GBM 128
#define GBN 64
#define GBK 16

__global__ void __launch_bounds__(256)
gemm_all(const float* __restrict__ nfeats, const float* __restrict__ dstf,
         const float* __restrict__ W_nj)
{
    const float *A, *B, *bias;
    float *C;
    int N, n0;
    if (blockIdx.y < 5) {
        A = nfeats; B = g_wcat; bias = g_bcat; C = g_proj;
        N = NCAT; n0 = blockIdx.y * GBN;
    } else {
        A = dstf; B = W_nj; bias = nullptr; C = g_fnj;
        N = HE; n0 = 0;
    }
    const int M  = N_SRC;          // == N_DST
    const int m0 = blockIdx.x * GBM;

    __shared__ float As[2][GBK][GBM + 4];
    __shared__ float Bs[2][GBK][GBN];

    const int tid = threadIdx.x;
    const int tr  = tid >> 3;      // 0..31 -> rows tr*4..+3
    const int tc  = tid & 7;       // 0..7  -> cols tc*8..+7

    // per-thread global-load slots
    const int am[2] = { (tid)        >> 2, (tid + 256) >> 2 };
    const int ak[2] = { (tid)        & 3,  (tid + 256) & 3  };
    const int bk = tid >> 4, bn = tid & 15;

    float4 ra[2], rb;
    const float4 z4 = make_float4(0.f, 0.f, 0.f, 0.f);

    auto gload = [&](int k0) {
#pragma unroll
        for (int t = 0; t < 2; t++) {
            int gm = m0 + am[t];
            ra[t] = (gm < M) ? *(const float4*)(A + (size_t)gm * IN_NODE + k0 + ak[t] * 4)
                             : z4;
        }
        rb = *(const float4*)(B + (size_t)(k0 + bk) * N + n0 + bn * 4);
    };
    auto sstore = [&](int buf) {
#pragma unroll
        for (int t = 0; t < 2; t++) {
            As[buf][ak[t] * 4 + 0][am[t]] = ra[t].x;
            As[buf][ak[t] * 4 + 1][am[t]] = ra[t].y;
            As[buf][ak[t] * 4 + 2][am[t]] = ra[t].z;
            As[buf][ak[t] * 4 + 3][am[t]] = ra[t].w;
        }
        *(float4*)&Bs[buf][bk][bn * 4] = rb;
    };

    float acc[4][8];
#pragma unroll
    for (int i = 0; i < 4; i++)
#pragma unroll
        for (int j = 0; j < 8; j++) acc[i][j] = 0.f;

    gload(0);
    sstore(0);
    __syncthreads();

#pragma unroll
    for (int kk = 0; kk < IN_NODE / GBK; kk++) {
        int buf = kk & 1;
        if (kk < IN_NODE / GBK - 1) gload((kk + 1) * GBK);
#pragma unroll
        for (int k = 0; k < GBK; k++) {
            float4 av  = *(const float4*)&As[buf][k][tr * 4];
            float4 bv0 = *(const float4*)&Bs[buf][k][tc * 8];
            float4 bv1 = *(const float4*)&Bs[buf][k][tc * 8 + 4];
            float a[4] = {av.x, av.y, av.z, av.w};
            float b[8] = {bv0.x, bv0.y, bv0.z, bv0.w, bv1.x, bv1.y, bv1.z, bv1.w};
#pragma unroll
            for (int i = 0; i < 4; i++)
#pragma unroll
                for (int j = 0; j < 8; j++)
                    acc[i][j] = fmaf(a[i], b[j], acc[i][j]);
        }
        if (kk < IN_NODE / GBK - 1) {
            sstore(buf ^ 1);
            __syncthreads();
        }
    }

    // epilogue
    float bsv[8] = {0.f};
    if (bias) {
        float4 b0 = *(const float4*)(bias + n0 + tc * 8);
        float4 b1 = *(const float4*)(bias + n0 + tc * 8 + 4);
        bsv[0]=b0.x; bsv[1]=b0.y; bsv[2]=b0.z; bsv[3]=b0.w;
        bsv[4]=b1.x; bsv[5]=b1.y; bsv[6]=b1.z; bsv[7]=b1.w;
    }
#pragma unroll
    for (int i = 0; i < 4; i++) {
        int gm = m0 + tr * 4 + i;
        if (gm < M) {
#pragma unroll
            for (int j = 0; j < 8; j += 4) {
                float4 v = make_float4(acc[i][j] + bsv[j], acc[i][j+1] + bsv[j+1],
                                       acc[i][j+2] + bsv[j+2], acc[i][j+3] + bsv[j+3]);
                *(float4*)(C + (size_t)gm * N + n0 + tc * 8 + j) = v;
            }
        }
    }
}

// ---------------- fused edge attention: logit -> exp -> segment sum --------
// No max-subtraction: |logit| <~ 2 here, exp() is safe, and a/s ratio is
// mathematically identical to the max-stabilized form.
// 16 threads per edge.
__global__ void __launch_bounds__(256)
edge_attn(const int* __restrict__ src, const int* __restrict__ dst,
          const float* __restrict__ reward,
          const float* __restrict__ attn, const float* __restrict__ b_e)
{
    int gi   = blockIdx.x * blockDim.x + threadIdx.x;
    int e    = gi >> 4;
    int lane = gi & 15;
    int w    = threadIdx.x & 31;       // warp-local lane

    int si = src[e];
    int d  = dst[e];
    float r = reward[e];

    float4 f  = *(const float4*)(g_proj + (size_t)si * NCAT + HN + lane * 4);
    float4 nj = *(const float4*)(g_fnj + (size_t)d * HE + lane * 4);
    float4 ws = ((const float4*)g_wsum)[lane];
    float4 be = ((const float4*)b_e)[lane];

    f.x = leaky(f.x + nj.x + r * ws.x + be.x);
    f.y = leaky(f.y + nj.y + r * ws.y + be.y);
    f.z = leaky(f.z + nj.z + r * ws.z + be.z);
    f.w = leaky(f.w + nj.w + r * ws.w + be.w);

    float4 at = ((const float4*)attn)[lane];
    float p = f.x * at.x + f.y * at.y + f.z * at.z + f.w * at.w;
    p += __shfl_xor_sync(0xffffffffu, p, 1);
    p += __shfl_xor_sync(0xffffffffu, p, 2);
    // quad q holds logit of head q (all 4 lanes). Move head h to lane h of the
    // 16-group: lane L reads from (group base) + (L&3)*4.
    float ph = __shfl_sync(0xffffffffu, p, (w & 16) + ((w & 3) << 2));

    if (lane < 4) {
        float a = __expf(ph);
        g_a[(size_t)e * NHEAD + lane] = a;
        redAddF1(g_s + (size_t)d * NHEAD + lane, a);
    }
}

// ---------------- head-combined weighted aggregation -----------------------
// out[d,f] += sum_h (a_h/s_h) * h_src[src, h, f]   (64 atomic floats/edge)
__global__ void __launch_bounds__(256)
edge_agg(const int* __restrict__ src, const int* __restrict__ dst,
         float* __restrict__ out)
{
    int gi   = blockIdx.x * blockDim.x + threadIdx.x;
    int e    = gi >> 4;
    int lane = gi & 15;

    int si = src[e];
    int d  = dst[e];

    float4 av = *(const float4*)(g_a + (size_t)e * NHEAD);
    float4 sv = *(const float4*)(g_s + (size_t)d * NHEAD);
    float a0 = av.x / (sv.x > 0.f ? sv.x : 1.f);
    float a1 = av.y / (sv.y > 0.f ? sv.y : 1.f);
    float a2 = av.z / (sv.z > 0.f ? sv.z : 1.f);
    float a3 = av.w / (sv.w > 0.f ? sv.w : 1.f);

    const float4* hp = (const float4*)(g_proj + (size_t)si * NCAT);
    float4 v0 = hp[lane];
    float4 v1 = hp[16 + lane];
    float4 v2 = hp[32 + lane];
    float4 v3 = hp[48 + lane];

    float4 acc;
    acc.x = a0 * v0.x + a1 * v1.x + a2 * v2.x + a3 * v3.x;
    acc.y = a0 * v0.y + a1 * v1.y + a2 * v2.y + a3 * v3.y;
    acc.z = a0 * v0.z + a1 * v1.z + a2 * v2.z + a3 * v3.z;
    acc.w = a0 * v0.w + a1 * v1.w + a2 * v2.w + a3 * v3.w;

    redAddF4((float4*)out + (size_t)d * 16 + lane, acc);
}

// ---------------- finalize: relu(mean over heads) --------------------------
__global__ void __launch_bounds__(256)
finalize(float* __restrict__ out)
{
    int i = blockIdx.x * blockDim.x + threadIdx.x;   // exact 3,200,000
    out[i] = fmaxf(out[i] * 0.25f, 0.f);
}

// ---------------- launch ----------------
extern "C" void kernel_launch(void* const* d_in, const int* in_sizes, int n_in,
                              void* d_out, int out_size)
{
    const float* nfeats  = (const float*)d_in[0];
    const float* dstf    = (const float*)d_in[1];
    const float* reward  = (const float*)d_in[2];
    const int*   src     = (const int*)  d_in[3];
    const int*   dst     = (const int*)  d_in[4];
    const float* W_ns    = (const float*)d_in[5];
    const float* b_ns    = (const float*)d_in[6];
    const float* W_ni    = (const float*)d_in[7];
    const float* W_nj    = (const float*)d_in[8];
    const float* W_fij   = (const float*)d_in[9];
    const float* attn    = (const float*)d_in[10];
    const float* b_e     = (const float*)d_in[11];
    float* out = (float*)d_out;

    init_kernel<<<OUT_ELEMS / 256, 256>>>(out);
    prep_misc<<<1, NCAT>>>(W_fij, b_ns);
    prep_wcat<<<IN_NODE * NCAT / 256, 256>>>(W_ns, W_ni);

    dim3 gg((N_SRC + GBM - 1) / GBM, 6);   // 391 x 6: all three projections
    gemm_all<<<gg, 256>>>(nfeats, dstf, W_nj);

    edge_attn<<<E_NUM * 16 / 256, 256>>>(src, dst, reward, attn, b_e);
    edge_agg <<<E_NUM * 16 / 256, 256>>>(src, dst, out);
    finalize <<<OUT_ELEMS / 256, 256>>>(out);
}

// round 5
// speedup vs baseline: 1.5935x; 1.5935x over previous
#include <cuda_runtime.h>
#include <math.h>
#include <stdint.h>

// ---------------- problem constants ----------------
#define N_SRC   50000
#define N_DST   50000
#define E_NUM   800000
#define IN_NODE 128
#define OUT_NODE 64
#define NHEAD   4
#define HN      (NHEAD*OUT_NODE)   // 256
#define HE      64                 // NHEAD*OUT_EDGE
#define NCAT    (HN + HE)          // 320 = [W_ns | W_ni] output cols
#define SLOPE   0.01f
#define OUT_ELEMS (N_DST*OUT_NODE) // 3,200,000

// ---------------- scratch (device globals; allocation-free) ----------------
__device__ __align__(16) float g_proj[(size_t)N_SRC * NCAT];   // 64 MB
__device__ __align__(16) float g_fnj [(size_t)N_DST * HE];     // 12.8 MB
__device__ __align__(16) float g_a   [(size_t)E_NUM * NHEAD];
__device__ __align__(16) float g_s   [(size_t)N_DST * NHEAD];
__device__ __align__(16) float g_wcat[IN_NODE * NCAT];         // [W_ns | W_ni]
__device__ __align__(16) float g_bcat[NCAT];                   // [b_ns | 0]
__device__ __align__(16) float g_wsum[HE];                     // colsum(W_fij)

// ---------------- helpers ----------------
__device__ __forceinline__ void redAddF4(float4* p, float4 v) {
    asm volatile("red.global.add.v4.f32 [%0], {%1, %2, %3, %4};"
                 :: "l"(__cvta_generic_to_global(p)),
                    "f"(v.x), "f"(v.y), "f"(v.z), "f"(v.w)
                 : "memory");
}
__device__ __forceinline__ void redAddF1(float* p, float v) {
    asm volatile("red.global.add.f32 [%0], %1;"
                 :: "l"(__cvta_generic_to_global(p)), "f"(v) : "memory");
}
__device__ __forceinline__ float leaky(float x) {
    return x >= 0.f ? x : SLOPE * x;
}
__device__ __forceinline__ uint32_t f2tf(float f) {
    uint32_t r;
    asm("cvt.rna.tf32.f32 %0, %1;" : "=r"(r) : "f"(f));
    return r;
}
__device__ __forceinline__ void mma_tf32(float* d, const uint32_t* a, const uint32_t* b) {
    asm volatile(
        "mma.sync.aligned.m16n8k8.row.col.f32.tf32.tf32.f32 "
        "{%0,%1,%2,%3}, {%4,%5,%6,%7}, {%8,%9}, {%0,%1,%2,%3};\n"
        : "+f"(d[0]), "+f"(d[1]), "+f"(d[2]), "+f"(d[3])
        : "r"(a[0]), "r"(a[1]), "r"(a[2]), "r"(a[3]), "r"(b[0]), "r"(b[1]));
}

// ---------------- init: zero out, s=0 ----------------
__global__ void init_kernel(float* __restrict__ out) {
    int i = blockIdx.x * blockDim.x + threadIdx.x;   // exact 3,200,000
    out[i] = 0.f;
    if (i < N_DST * NHEAD) g_s[i] = 0.f;
}

// ---------------- prep: wsum, bias concat ----------------
__global__ void prep_misc(const float* __restrict__ W_fij,
                          const float* __restrict__ b_ns) {
    int t = threadIdx.x;   // 320 threads
    if (t < HE) {
        float s = 0.f;
#pragma unroll
        for (int k = 0; k < 16; k++) s += W_fij[k * HE + t];
        g_wsum[t] = s;
    }
    g_bcat[t] = (t < HN) ? b_ns[t] : 0.f;
}

// ---------------- prep: weight concat [W_ns | W_ni] -> 128 x 320 -----------
__global__ void prep_wcat(const float* __restrict__ W_ns,
                          const float* __restrict__ W_ni) {
    int i = blockIdx.x * blockDim.x + threadIdx.x;   // exact 128*320 = 40960
    int k = i / NCAT, n = i % NCAT;
    g_wcat[i] = (n < HN) ? W_ns[k * HN + n] : W_ni[k * HE + (n - HN)];
}

// ---------------- tf32 tensor-core GEMM ----------------
// grid = (391, 6).  y<5: g_proj = nfeats @ [W_ns|W_ni] + [b_ns|0]  (N=320)
//                   y==5: g_fnj = dst_feats @ W_nj                  (N=64)
// Tile 128x64, BK=32, 256 threads (8 warps), warp = 32x32 macro-tile via
// mma.sync m16n8k8 tf32.
// Smem pads: A stride 36 -> frag-load bank = 4*g4+k4, all 32 distinct.
//            B stride 72 (64 data + 8 pad) -> bank = 8*k4+g4, all distinct.
#define GBM 128
#define GBN 64
#define GBK 32
#define ASTR 36
#define BSTR 72

__global__ void __launch_bounds__(256)
gemm_all(const float* __restrict__ nfeats, const float* __restrict__ dstf,
         const float* __restrict__ W_nj)
{
    const float *A, *B, *bias;
    float *C;
    int N, n0;
    if (blockIdx.y < 5) {
        A = nfeats; B = g_wcat; bias = g_bcat; C = g_proj;
        N = NCAT; n0 = blockIdx.y * GBN;
    } else {
        A = dstf; B = W_nj; bias = nullptr; C = g_fnj;
        N = HE; n0 = 0;
    }
    const int M  = N_SRC;          // == N_DST
    const int m0 = blockIdx.x * GBM;

    __shared__ uint32_t As[GBM * ASTR];   // [row][k], stride 36
    __shared__ uint32_t Bs[GBK * BSTR];   // [k][n],  stride 72

    const int tid  = threadIdx.x;
    const int w    = tid >> 5;
    const int lane = tid & 31;
    const int g4   = lane >> 2;    // group id 0..7
    const int k4   = lane & 3;     // thread-in-group
    const int mw   = w & 3;        // warp m index (rows mw*32)
    const int nw   = w >> 2;       // warp n index (cols nw*32)

    // staging slots
    const int ar[4] = { (tid) >> 3, (tid+256) >> 3, (tid+512) >> 3, (tid+768) >> 3 };
    const int ac    = tid & 7;
    const int brow[2] = { tid >> 4, (tid+256) >> 4 };
    const int bn4   = tid & 15;

    float4 av[4], bv[2];
    const float4 z4 = make_float4(0.f, 0.f, 0.f, 0.f);

    float acc[2][4][4];
#pragma unroll
    for (int t = 0; t < 2; t++)
#pragma unroll
        for (int nt = 0; nt < 4; nt++)
#pragma unroll
            for (int j = 0; j < 4; j++) acc[t][nt][j] = 0.f;

    auto gload = [&](int k0) {
#pragma unroll
        for (int i = 0; i < 4; i++) {
            int gm = m0 + ar[i];
            av[i] = (gm < M) ? *(const float4*)(A + (size_t)gm * IN_NODE + k0 + ac * 4)
                             : z4;
        }
#pragma unroll
        for (int i = 0; i < 2; i++)
            bv[i] = *(const float4*)(B + (size_t)(k0 + brow[i]) * N + n0 + bn4 * 4);
    };
    auto sstore = [&]() {
#pragma unroll
        for (int i = 0; i < 4; i++) {
            uint32_t* p = &As[ar[i] * ASTR + ac * 4];
            p[0] = f2tf(av[i].x); p[1] = f2tf(av[i].y);
            p[2] = f2tf(av[i].z); p[3] = f2tf(av[i].w);
        }
#pragma unroll
        for (int i = 0; i < 2; i++) {
            uint32_t* p = &Bs[brow[i] * BSTR + bn4 * 4];
            p[0] = f2tf(bv[i].x); p[1] = f2tf(bv[i].y);
            p[2] = f2tf(bv[i].z); p[3] = f2tf(bv[i].w);
        }
    };

    gload(0);
#pragma unroll
    for (int kk = 0; kk < IN_NODE / GBK; kk++) {
        if (kk) __syncthreads();
        sstore();
        __syncthreads();
        if (kk < IN_NODE / GBK - 1) gload((kk + 1) * GBK);

#pragma unroll
        for (int kt = 0; kt < 4; kt++) {
            uint32_t afr[2][4], bfr[4][2];
            const int kb = kt * 8;
#pragma unroll
            for (int t = 0; t < 2; t++) {
                int rbase = (mw * 32 + t * 16 + g4) * ASTR + kb + k4;
                afr[t][0] = As[rbase];
                afr[t][1] = As[rbase + 8 * ASTR];
                afr[t][2] = As[rbase + 4];
                afr[t][3] = As[rbase + 8 * ASTR + 4];
            }
#pragma unroll
            for (int nt = 0; nt < 4; nt++) {
                int n = nw * 32 + nt * 8 + g4;
                bfr[nt][0] = Bs[(kb + k4) * BSTR + n];
                bfr[nt][1] = Bs[(kb + k4 + 4) * BSTR + n];
            }
#pragma unroll
            for (int t = 0; t < 2; t++)
#pragma unroll
                for (int nt = 0; nt < 4; nt++)
                    mma_tf32(acc[t][nt], afr[t], bfr[nt]);
        }
    }

    // epilogue: c0,c1 -> (row, col..col+1); c2,c3 -> (row+8, col..col+1)
#pragma unroll
    for (int t = 0; t < 2; t++) {
        int r0 = m0 + mw * 32 + t * 16 + g4;
#pragma unroll
        for (int nt = 0; nt < 4; nt++) {
            int col = n0 + nw * 32 + nt * 8 + 2 * k4;
            float b0 = 0.f, b1 = 0.f;
            if (bias) { b0 = bias[col]; b1 = bias[col + 1]; }
            if (r0 < M)
                *(float2*)(C + (size_t)r0 * N + col) =
                    make_float2(acc[t][nt][0] + b0, acc[t][nt][1] + b1);
            if (r0 + 8 < M)
                *(float2*)(C + (size_t)(r0 + 8) * N + col) =
                    make_float2(acc[t][nt][2] + b0, acc[t][nt][3] + b1);
        }
    }
}

// ---------------- fused edge attention: logit -> exp -> segment sum --------
// No max-subtraction: |logit| <~ 2 here, exp() safe; ratio identical.
__global__ void __launch_bounds__(256)
edge_attn(const int* __restrict__ src, const int* __restrict__ dst,
          const float* __restrict__ reward,
          const float* __restrict__ attn, const float* __restrict__ b_e)
{
    int gi   = blockIdx.x * blockDim.x + threadIdx.x;
    int e    = gi >> 4;
    int lane = gi & 15;
    int w    = threadIdx.x & 31;       // warp-local lane

    int si = src[e];
    int d  = dst[e];
    float r = reward[e];

    float4 f  = *(const float4*)(g_proj + (size_t)si * NCAT + HN + lane * 4);
    float4 nj = *(const float4*)(g_fnj + (size_t)d * HE + lane * 4);
    float4 ws = ((const float4*)g_wsum)[lane];
    float4 be = ((const float4*)b_e)[lane];

    f.x = leaky(f.x + nj.x + r * ws.x + be.x);
    f.y = leaky(f.y + nj.y + r * ws.y + be.y);
    f.z = leaky(f.z + nj.z + r * ws.z + be.z);
    f.w = leaky(f.w + nj.w + r * ws.w + be.w);

    float4 at = ((const float4*)attn)[lane];
    float p = f.x * at.x + f.y * at.y + f.z * at.z + f.w * at.w;
    p += __shfl_xor_sync(0xffffffffu, p, 1);
    p += __shfl_xor_sync(0xffffffffu, p, 2);
    float ph = __shfl_sync(0xffffffffu, p, (w & 16) + ((w & 3) << 2));

    if (lane < 4) {
        float a = __expf(ph);
        g_a[(size_t)e * NHEAD + lane] = a;
        redAddF1(g_s + (size_t)d * NHEAD + lane, a);
    }
}

// ---------------- head-combined weighted aggregation -----------------------
__global__ void __launch_bounds__(256)
edge_agg(const int* __restrict__ src, const int* __restrict__ dst,
         float* __restrict__ out)
{
    int gi   = blockIdx.x * blockDim.x + threadIdx.x;
    int e    = gi >> 4;
    int lane = gi & 15;

    int si = src[e];
    int d  = dst[e];

    float4 avv = *(const float4*)(g_a + (size_t)e * NHEAD);
    float4 sv  = *(const float4*)(g_s + (size_t)d * NHEAD);
    float a0 = avv.x / (sv.x > 0.f ? sv.x : 1.f);
    float a1 = avv.y / (sv.y > 0.f ? sv.y : 1.f);
    float a2 = avv.z / (sv.z > 0.f ? sv.z : 1.f);
    float a3 = avv.w / (sv.w > 0.f ? sv.w : 1.f);

    const float4* hp = (const float4*)(g_proj + (size_t)si * NCAT);
    float4 v0 = hp[lane];
    float4 v1 = hp[16 + lane];
    float4 v2 = hp[32 + lane];
    float4 v3 = hp[48 + lane];

    float4 acc;
    acc.x = a0 * v0.x + a1 * v1.x + a2 * v2.x + a3 * v3.x;
    acc.y = a0 * v0.y + a1 * v1.y + a2 * v2.y + a3 * v3.y;
    acc.z = a0 * v0.z + a1 * v1.z + a2 * v2.z + a3 * v3.z;
    acc.w = a0 * v0.w + a1 * v1.w + a2 * v2.w + a3 * v3.w;

    redAddF4((float4*)out + (size_t)d * 16 + lane, acc);
}

// ---------------- finalize: relu(mean over heads) --------------------------
__global__ void __launch_bounds__(256)
finalize(float* __restrict__ out)
{
    int i = blockIdx.x * blockDim.x + threadIdx.x;   // exact 3,200,000
    out[i] = fmaxf(out[i] * 0.25f, 0.f);
}

// ---------------- launch ----------------
extern "C" void kernel_launch(void* const* d_in, const int* in_sizes, int n_in,
                              void* d_out, int out_size)
{
    const float* nfeats  = (const float*)d_in[0];
    const float* dstf    = (const float*)d_in[1];
    const float* reward  = (const float*)d_in[2];
    const int*   src     = (const int*)  d_in[3];
    const int*   dst     = (const int*)  d_in[4];
    const float* W_ns    = (const float*)d_in[5];
    const float* b_ns    = (const float*)d_in[6];
    const float* W_ni    = (const float*)d_in[7];
    const float* W_nj    = (const float*)d_in[8];
    const float* W_fij   = (const float*)d_in[9];
    const float* attn    = (const float*)d_in[10];
    const float* b_e     = (const float*)d_in[11];
    float* out = (float*)d_out;

    init_kernel<<<OUT_ELEMS / 256, 256>>>(out);
    prep_misc<<<1, NCAT>>>(W_fij, b_ns);
    prep_wcat<<<IN_NODE * NCAT / 256, 256>>>(W_ns, W_ni);

    dim3 gg((N_SRC + GBM - 1) / GBM, 6);   // 391 x 6: all three projections
    gemm_all<<<gg, 256>>>(nfeats, dstf, W_nj);

    edge_attn<<<E_NUM * 16 / 256, 256>>>(src, dst, reward, attn, b_e);
    edge_agg <<<E_NUM * 16 / 256, 256>>>(src, dst, out);
    finalize <<<OUT_ELEMS / 256, 256>>>(out);
}